// round 15
// baseline (speedup 1.0000x reference)
#include <cuda_runtime.h>
#include <cstdint>
#include <cfloat>

// SQuant 4-bit adaptive rounding (round 15 = round 11 + named-barrier
// producer/consumer tail: warps 1-7 arrive-and-go, only warp 0 waits).
// 256 threads/block, 4 kernel-groups/thread, 4 blocks/SM.

#define NROWS   1024
#define ROWLEN  9216
#define NV4     2304
#define NT      256
#define NGROUP  4
#define NWARP   8
#define NCAND   (NT * NGROUP)   // 1024

// shared layout (dynamic):
//   [0,     36864) s_w   : row of 9216 floats
//       after pass 1, aliased: [0,4096) s_U (1024 u32), [4096,8192) s_IV
//   [36864, 46080) s_r   : 9216 int8 rounded values
//   [46080, 46144) s_red : 16 floats (per-warp max[8], min[8])
//   [46144, 46176) s_sum : 8 floats  (per-warp residual-error sums)
#define OFF_R   36864
#define OFF_RED 46080
#define OFF_SUM 46144
#define SMEM_BYTES 46176

#define NBAR_SYNC(id)   asm volatile("bar.sync %0, %1;"   :: "r"(id), "r"(NT) : "memory")
#define NBAR_ARRIVE(id) asm volatile("bar.arrive %0, %1;" :: "r"(id), "r"(NT) : "memory")

__device__ __forceinline__ float warpSum(float v) {
#pragma unroll
    for (int o = 16; o; o >>= 1) v += __shfl_xor_sync(0xffffffffu, v, o);
    return v;
}
__device__ __forceinline__ float warpMaxR(float v) {
#pragma unroll
    for (int o = 16; o; o >>= 1) v = fmaxf(v, __shfl_xor_sync(0xffffffffu, v, o));
    return v;
}
__device__ __forceinline__ float warpMinR(float v) {
#pragma unroll
    for (int o = 16; o; o >>= 1) v = fminf(v, __shfl_xor_sync(0xffffffffu, v, o));
    return v;
}

__global__ void __launch_bounds__(NT, 4)
squant_kernel(const float* __restrict__ w, float* __restrict__ out)
{
    extern __shared__ unsigned char smem[];
    float*       s_w   = (float*)smem;
    unsigned*    s_U   = (unsigned*)smem;              // aliases s_w after pass 1
    unsigned*    s_IVs = (unsigned*)(smem + 4096);     // aliases s_w after pass 1
    signed char* s_r   = (signed char*)(smem + OFF_R);
    float*       s_red = (float*)(smem + OFF_RED);
    float*       s_sum = (float*)(smem + OFF_SUM);

    const int tid  = threadIdx.x;
    const int lane = tid & 31;
    const int wid  = tid >> 5;

    const float4* __restrict__ w4 = (const float4*)(w + (size_t)blockIdx.x * ROWLEN);
    float* __restrict__ orow = out + (size_t)blockIdx.x * ROWLEN;
    float4* sw4 = (float4*)s_w;

    // ---- vectorized load + min/max (1 barrier) ----
    float vmax = -FLT_MAX, vmin = FLT_MAX;
#pragma unroll
    for (int i = tid; i < NV4; i += NT) {
        float4 v = w4[i];
        sw4[i] = v;
        vmax = fmaxf(vmax, fmaxf(fmaxf(v.x, v.y), fmaxf(v.z, v.w)));
        vmin = fminf(vmin, fminf(fminf(v.x, v.y), fminf(v.z, v.w)));
    }
    vmax = warpMaxR(vmax);
    vmin = warpMinR(vmin);
    if (lane == 0) { s_red[wid] = vmax; s_red[NWARP + wid] = vmin; }
    __syncthreads();                       // also publishes s_w
    float m = s_red[0], n = s_red[NWARP];
#pragma unroll
    for (int i = 1; i < NWARP; i++) {
        m = fmaxf(m, s_red[i]);
        n = fminf(n, s_red[NWARP + i]);
    }
    const float scale = 15.0f / fmaxf(m - n, 1e-8f);
    const float zp    = rintf(scale * n) + 8.0f;
    const float inv   = 1.0f / scale;
    const float zpinv = zp * inv;

    // ---- pass 1: SQuant-K, 4 groups/thread, float-domain selection ----
    // (textually identical to the proven round-5/11 kernel)
    float    Pup[NGROUP], Pdn[NGROUP];
    unsigned IVup[NGROUP], IVdn[NGROUP];   // (elem_idx << 8) | (val + 32)
    float er_tot = 0.f;

#pragma unroll
    for (int g = 0; g < NGROUP; g++) {
        const int base = (g * NT + tid) * 9;
        float rv[9], ev[9], pup[9], pdn[9];
        float e = 0.f;
#pragma unroll
        for (int j = 0; j < 9; j++) {
            float qq = fmaf(scale, s_w[base + j], -zp);
            float rr = rintf(qq);
            float ee = rr - qq;
            rv[j] = rr; ev[j] = ee;
            pup[j] = (ee < 0.f && qq <  7.f) ? -ee : 0.f;
            pdn[j] = (ee > 0.f && qq > -8.f) ?  ee : 0.f;
            e += ee;
        }
        const bool  is_up = (e < 0.f);
        const float dir   = is_up ? 1.f : -1.f;
        float nf = rintf(fabsf(e));
        nf = fminf(nf, 8.f);

        float pf[9];
#pragma unroll
        for (int j = 0; j < 9; j++) pf[j] = is_up ? pup[j] : pdn[j];

        float rk[9];
#pragma unroll
        for (int j = 0; j < 9; j++) rk[j] = 0.f;
#pragma unroll
        for (int j = 1; j < 9; j++)
#pragma unroll
            for (int i = 0; i < j; i++) {
                bool c = pf[i] >= pf[j];
                rk[j] += c ? 1.f : 0.f;
                rk[i] += c ? 0.f : 1.f;
            }

        const float nfm1 = nf - 1.f;
        float er = 0.f;
        float pN = 0.f, pL = 0.f, vN = 0.f, vL = 0.f;
        int iN = 0, iL = 0;
#pragma unroll
        for (int j = 0; j < 9; j++) {
            bool  cnd   = pf[j] > 0.f;
            float delta = cnd ? dir : 0.f;
            bool  f     = rk[j] < nf;
            float nr = f ? (rv[j] + delta) : rv[j];
            float ne = f ? (cnd ? (ev[j] + delta) : 0.f) : ev[j];
            er += ne;
            s_r[base + j] = (signed char)__float2int_rn(nr);
            if (rk[j] == nf)   { pN = pf[j]; vN = rv[j] + delta; iN = j; }
            if (rk[j] == nfm1) { pL = pf[j]; vL = rv[j];         iL = j; }
        }
        er_tot += er;

        const bool  hasL = (nf > 0.f);
        const float priN = pN;
        const float priL = hasL ? (1.f - pL) : 0.f;
        const float valL = hasL ? vL : vN;
        const int   idxN = base + iN;
        const int   idxL = hasL ? (base + iL) : idxN;
        const unsigned ivN = ((unsigned)idxN << 8) | (unsigned)(__float2int_rn(vN)   + 32);
        const unsigned ivL = ((unsigned)idxL << 8) | (unsigned)(__float2int_rn(valL) + 32);

        if (is_up) { Pup[g] = priN; IVup[g] = ivN; Pdn[g] = priL; IVdn[g] = ivL; }
        else       { Pdn[g] = priN; IVdn[g] = ivN; Pup[g] = priL; IVup[g] = ivL; }
    }

    // ---- row residual-error reduction (barrier #1; also retires s_w reads) ----
    {
        float s = warpSum(er_tot);
        if (lane == 0) s_sum[wid] = s;
    }
    __syncthreads();
    float e2 = s_sum[0];
#pragma unroll
    for (int i = 1; i < NWARP; i++) e2 += s_sum[i];

    const bool up2 = (e2 < 0.f);
    int k = (int)rintf(fabsf(e2));
    if (k > NCAND) k = NCAND;

    // dump chosen-direction candidates into the dead s_w region
#pragma unroll
    for (int g = 0; g < NGROUP; g++) {
        const int gi = g * NT + tid;
        s_U[gi]   = __float_as_uint(up2 ? Pup[g] : Pdn[g]);  // P >= 0 -> monotone bits
        s_IVs[gi] = up2 ? IVup[g] : IVdn[g];
    }

    // ---- decoupled tail: warps 1-7 arrive-and-go; only warp 0 waits ----
    if (wid == 0) {
        NBAR_SYNC(1);      // wait until all candidate dumps are visible
        unsigned win = 0;  // warp-0 winner mask over its 32 candidates
        unsigned u[32];
        if (k > 0) {
            // lane L owns candidates {m*128 + L*4 + q : m=0..7, q=0..3}
#pragma unroll
            for (int mm = 0; mm < 8; mm++) {
                uint4 t = *(const uint4*)(smem + (mm * 512 + lane * 16));
                u[mm * 4 + 0] = t.x; u[mm * 4 + 1] = t.y;
                u[mm * 4 + 2] = t.z; u[mm * 4 + 3] = t.w;
            }
            unsigned lo = 0u, hi = 0x3F800000u;   // cnt(>=lo)>=k, cnt(>=hi+1)<k
            bool found = false;
            unsigned thr = 0;
            while (lo < hi) {
                float midf = 0.5f * (__uint_as_float(lo) + __uint_as_float(hi));
                unsigned mid = __float_as_uint(midf);
                if (mid <= lo) mid = lo + 1;
                else if (mid > hi) mid = hi;
                int cl = 0;
#pragma unroll
                for (int i = 0; i < 32; i++) cl += (u[i] >= mid) ? 1 : 0;
                int c = __reduce_add_sync(0xffffffffu, cl);
                if (c == k) { thr = mid; found = true; break; }
                if (c > k) lo = mid; else hi = mid - 1;
            }
            if (found) {
#pragma unroll
                for (int i = 0; i < 32; i++)
                    win |= (u[i] >= thr) ? (1u << i) : 0u;
            } else {
                // exact ties at the k-th priority: resolve by ascending element index
                const unsigned Uk = lo;
                int clg = 0;
#pragma unroll
                for (int i = 0; i < 32; i++) clg += (u[i] > Uk) ? 1 : 0;
                int cGT = __reduce_add_sync(0xffffffffu, clg);
                int rem = k - cGT;                  // >= 1
                int ilo = 0, ihi = ROWLEN, mI = ROWLEN;
                for (;;) {
                    mI = (ilo + ihi + 1) >> 1;
                    int ct = 0;
#pragma unroll
                    for (int mm = 0; mm < 8; mm++) {
                        uint4 t = *(const uint4*)(smem + 4096 + (mm * 512 + lane * 16));
                        ct += (u[mm*4+0] == Uk && (int)(t.x >> 8) < mI) ? 1 : 0;
                        ct += (u[mm*4+1] == Uk && (int)(t.y >> 8) < mI) ? 1 : 0;
                        ct += (u[mm*4+2] == Uk && (int)(t.z >> 8) < mI) ? 1 : 0;
                        ct += (u[mm*4+3] == Uk && (int)(t.w >> 8) < mI) ? 1 : 0;
                    }
                    int c = __reduce_add_sync(0xffffffffu, ct);
                    if (c == rem) break;            // unique indices -> always reachable
                    if (c < rem) ilo = mI; else ihi = mI - 1;
                }
#pragma unroll
                for (int mm = 0; mm < 8; mm++) {
                    uint4 t = *(const uint4*)(smem + 4096 + (mm * 512 + lane * 16));
                    if (u[mm*4+0] > Uk || (u[mm*4+0] == Uk && (int)(t.x >> 8) < mI)) win |= 1u << (mm*4+0);
                    if (u[mm*4+1] > Uk || (u[mm*4+1] == Uk && (int)(t.y >> 8) < mI)) win |= 1u << (mm*4+1);
                    if (u[mm*4+2] > Uk || (u[mm*4+2] == Uk && (int)(t.z >> 8) < mI)) win |= 1u << (mm*4+2);
                    if (u[mm*4+3] > Uk || (u[mm*4+3] == Uk && (int)(t.w >> 8) < mI)) win |= 1u << (mm*4+3);
                }
            }
        }
        NBAR_SYNC(2);      // wait for epilogue STGs before patching same addresses
        if (k > 0 && win) {
#pragma unroll
            for (int mm = 0; mm < 8; mm++) {
                uint4 t = *(const uint4*)(smem + 4096 + (mm * 512 + lane * 16));
#pragma unroll
                for (int q = 0; q < 4; q++) {
                    if ((win >> (mm * 4 + q)) & 1u) {
                        unsigned ivv = (q == 0) ? t.x : (q == 1) ? t.y : (q == 2) ? t.z : t.w;
                        int   idx = (int)(ivv >> 8);
                        float vf  = (float)((int)(ivv & 0xFFu) - 32);
                        orow[idx] = fmaf(fminf(7.f, fmaxf(-8.f, vf)), inv, zpinv);
                    }
                }
            }
        }
    } else {
        NBAR_ARRIVE(1);    // publish dump, proceed immediately
        // ---- clip + dequantize epilogue (warps 1-7, concurrent with warp 0) ----
        float4* __restrict__ orow4 = (float4*)orow;
        const int* s_ri = (const int*)s_r;
        for (int i = tid - 32; i < NV4; i += NT - 32) {
            int p = s_ri[i];
            p = __vmins4(__vmaxs4(p, 0xF8F8F8F8), 0x07070707);   // clip bytes to [-8,7]
            float4 o;
            o.x = fmaf((float)(int)(signed char)(p),       inv, zpinv);
            o.y = fmaf((float)(int)(signed char)(p >> 8),  inv, zpinv);
            o.z = fmaf((float)(int)(signed char)(p >> 16), inv, zpinv);
            o.w = fmaf((float)(int)(signed char)(p >> 24), inv, zpinv);
            orow4[i] = o;
        }
        NBAR_ARRIVE(2);    // publish epilogue stores, exit without waiting
    }
}

extern "C" void kernel_launch(void* const* d_in, const int* in_sizes, int n_in,
                              void* d_out, int out_size)
{
    const float* w = (const float*)d_in[0];
    float* out = (float*)d_out;
    squant_kernel<<<NROWS, NT, SMEM_BYTES>>>(w, out);
}

// round 16
// speedup vs baseline: 1.0626x; 1.0626x over previous
#include <cuda_runtime.h>
#include <cstdint>
#include <cfloat>

// SQuant 4-bit adaptive rounding — FINAL (round 11 structure).
// 256 threads/block, 4 kernel-groups/thread, 4 blocks/SM.
// Pass 1: per-9-element SQuant-K flip pass, float-domain stable ranking,
//         int8 staging of rounded values in smem.
// Pass 2: per-row SQuant-C over the per-group boundary candidates; all
//         threads dump (priority, idx/val) into smem (aliasing dead s_w);
//         warp 0 finds the k-th largest via warp-local bisection (no block
//         barriers) CONCURRENTLY with warps 1-7 running the clip+dequant
//         epilogue; warp 0 then patches the <=k flipped elements in GMEM.

#define NROWS   1024
#define ROWLEN  9216
#define NV4     2304
#define NT      256
#define NGROUP  4
#define NWARP   8
#define NCAND   (NT * NGROUP)   // 1024

// shared layout (dynamic):
//   [0,     36864) s_w   : row of 9216 floats
//       after pass 1, aliased: [0,4096) s_U (1024 u32), [4096,8192) s_IV
//   [36864, 46080) s_r   : 9216 int8 rounded values
//   [46080, 46144) s_red : 16 floats (per-warp max[8], min[8])
//   [46144, 46176) s_sum : 8 floats  (per-warp residual-error sums)
#define OFF_R   36864
#define OFF_RED 46080
#define OFF_SUM 46144
#define SMEM_BYTES 46176

__device__ __forceinline__ float warpSum(float v) {
#pragma unroll
    for (int o = 16; o; o >>= 1) v += __shfl_xor_sync(0xffffffffu, v, o);
    return v;
}
__device__ __forceinline__ float warpMaxR(float v) {
#pragma unroll
    for (int o = 16; o; o >>= 1) v = fmaxf(v, __shfl_xor_sync(0xffffffffu, v, o));
    return v;
}
__device__ __forceinline__ float warpMinR(float v) {
#pragma unroll
    for (int o = 16; o; o >>= 1) v = fminf(v, __shfl_xor_sync(0xffffffffu, v, o));
    return v;
}

__global__ void __launch_bounds__(NT, 4)
squant_kernel(const float* __restrict__ w, float* __restrict__ out)
{
    extern __shared__ unsigned char smem[];
    float*       s_w   = (float*)smem;
    unsigned*    s_U   = (unsigned*)smem;              // aliases s_w after pass 1
    unsigned*    s_IVs = (unsigned*)(smem + 4096);     // aliases s_w after pass 1
    signed char* s_r   = (signed char*)(smem + OFF_R);
    float*       s_red = (float*)(smem + OFF_RED);
    float*       s_sum = (float*)(smem + OFF_SUM);

    const int tid  = threadIdx.x;
    const int lane = tid & 31;
    const int wid  = tid >> 5;

    const float4* __restrict__ w4 = (const float4*)(w + (size_t)blockIdx.x * ROWLEN);
    float* __restrict__ orow = out + (size_t)blockIdx.x * ROWLEN;
    float4* sw4 = (float4*)s_w;

    // ---- vectorized load + min/max (1 barrier) ----
    float vmax = -FLT_MAX, vmin = FLT_MAX;
#pragma unroll
    for (int i = tid; i < NV4; i += NT) {
        float4 v = w4[i];
        sw4[i] = v;
        vmax = fmaxf(vmax, fmaxf(fmaxf(v.x, v.y), fmaxf(v.z, v.w)));
        vmin = fminf(vmin, fminf(fminf(v.x, v.y), fminf(v.z, v.w)));
    }
    vmax = warpMaxR(vmax);
    vmin = warpMinR(vmin);
    if (lane == 0) { s_red[wid] = vmax; s_red[NWARP + wid] = vmin; }
    __syncthreads();                       // also publishes s_w
    float m = s_red[0], n = s_red[NWARP];
#pragma unroll
    for (int i = 1; i < NWARP; i++) {
        m = fmaxf(m, s_red[i]);
        n = fminf(n, s_red[NWARP + i]);
    }
    const float scale = 15.0f / fmaxf(m - n, 1e-8f);
    const float zp    = rintf(scale * n) + 8.0f;
    const float inv   = 1.0f / scale;
    const float zpinv = zp * inv;

    // ---- pass 1: SQuant-K, 4 groups/thread, float-domain selection ----
    float    Pup[NGROUP], Pdn[NGROUP];
    unsigned IVup[NGROUP], IVdn[NGROUP];   // (elem_idx << 8) | (val + 32)
    float er_tot = 0.f;

#pragma unroll
    for (int g = 0; g < NGROUP; g++) {
        const int base = (g * NT + tid) * 9;
        float rv[9], ev[9], pup[9], pdn[9];
        float e = 0.f;
#pragma unroll
        for (int j = 0; j < 9; j++) {
            float qq = fmaf(scale, s_w[base + j], -zp);
            float rr = rintf(qq);
            float ee = rr - qq;
            rv[j] = rr; ev[j] = ee;
            pup[j] = (ee < 0.f && qq <  7.f) ? -ee : 0.f;
            pdn[j] = (ee > 0.f && qq > -8.f) ?  ee : 0.f;
            e += ee;
        }
        const bool  is_up = (e < 0.f);
        const float dir   = is_up ? 1.f : -1.f;
        float nf = rintf(fabsf(e));
        nf = fminf(nf, 8.f);

        float pf[9];
#pragma unroll
        for (int j = 0; j < 9; j++) pf[j] = is_up ? pup[j] : pdn[j];

        float rk[9];
#pragma unroll
        for (int j = 0; j < 9; j++) rk[j] = 0.f;
#pragma unroll
        for (int j = 1; j < 9; j++)
#pragma unroll
            for (int i = 0; i < j; i++) {
                bool c = pf[i] >= pf[j];
                rk[j] += c ? 1.f : 0.f;
                rk[i] += c ? 0.f : 1.f;
            }

        const float nfm1 = nf - 1.f;
        float er = 0.f;
        float pN = 0.f, pL = 0.f, vN = 0.f, vL = 0.f;
        int iN = 0, iL = 0;
#pragma unroll
        for (int j = 0; j < 9; j++) {
            bool  cnd   = pf[j] > 0.f;
            float delta = cnd ? dir : 0.f;
            bool  f     = rk[j] < nf;
            float nr = f ? (rv[j] + delta) : rv[j];
            float ne = f ? (cnd ? (ev[j] + delta) : 0.f) : ev[j];
            er += ne;
            s_r[base + j] = (signed char)__float2int_rn(nr);
            if (rk[j] == nf)   { pN = pf[j]; vN = rv[j] + delta; iN = j; }
            if (rk[j] == nfm1) { pL = pf[j]; vL = rv[j];         iL = j; }
        }
        er_tot += er;

        const bool  hasL = (nf > 0.f);
        const float priN = pN;
        const float priL = hasL ? (1.f - pL) : 0.f;
        const float valL = hasL ? vL : vN;
        const int   idxN = base + iN;
        const int   idxL = hasL ? (base + iL) : idxN;
        const unsigned ivN = ((unsigned)idxN << 8) | (unsigned)(__float2int_rn(vN)   + 32);
        const unsigned ivL = ((unsigned)idxL << 8) | (unsigned)(__float2int_rn(valL) + 32);

        if (is_up) { Pup[g] = priN; IVup[g] = ivN; Pdn[g] = priL; IVdn[g] = ivL; }
        else       { Pdn[g] = priN; IVdn[g] = ivN; Pup[g] = priL; IVup[g] = ivL; }
    }

    // ---- row residual-error reduction (barrier #1; also retires s_w reads) ----
    {
        float s = warpSum(er_tot);
        if (lane == 0) s_sum[wid] = s;
    }
    __syncthreads();
    float e2 = s_sum[0];
#pragma unroll
    for (int i = 1; i < NWARP; i++) e2 += s_sum[i];

    const bool up2 = (e2 < 0.f);
    int k = (int)rintf(fabsf(e2));
    if (k > NCAND) k = NCAND;

    // dump chosen-direction candidates into the dead s_w region
#pragma unroll
    for (int g = 0; g < NGROUP; g++) {
        const int gi = g * NT + tid;
        s_U[gi]   = __float_as_uint(up2 ? Pup[g] : Pdn[g]);  // P >= 0 -> monotone bits
        s_IVs[gi] = up2 ? IVup[g] : IVdn[g];
    }
    __syncthreads();   // barrier #2: publish s_U/s_IV (s_r already published)

    // ---- overlapped tail: warp 0 selects, warps 1-7 run the epilogue ----
    unsigned win = 0;          // warp-0 winner mask over its 32 candidates
    unsigned u[32];

    if (wid == 0 && k > 0) {
        // lane L owns candidates {m*128 + L*4 + q : m=0..7, q=0..3}
#pragma unroll
        for (int mm = 0; mm < 8; mm++) {
            uint4 t = *(const uint4*)(smem + (mm * 512 + lane * 16));
            u[mm * 4 + 0] = t.x; u[mm * 4 + 1] = t.y;
            u[mm * 4 + 2] = t.z; u[mm * 4 + 3] = t.w;
        }
        unsigned lo = 0u, hi = 0x3F800000u;   // cnt(>=lo)>=k, cnt(>=hi+1)<k
        bool found = false;
        unsigned thr = 0;
        while (lo < hi) {
            float midf = 0.5f * (__uint_as_float(lo) + __uint_as_float(hi));
            unsigned mid = __float_as_uint(midf);
            if (mid <= lo) mid = lo + 1;
            else if (mid > hi) mid = hi;
            int cl = 0;
#pragma unroll
            for (int i = 0; i < 32; i++) cl += (u[i] >= mid) ? 1 : 0;
            int c = __reduce_add_sync(0xffffffffu, cl);
            if (c == k) { thr = mid; found = true; break; }
            if (c > k) lo = mid; else hi = mid - 1;
        }
        if (found) {
#pragma unroll
            for (int i = 0; i < 32; i++)
                win |= (u[i] >= thr) ? (1u << i) : 0u;
        } else {
            // exact ties at the k-th priority: resolve by ascending element index
            const unsigned Uk = lo;
            int clg = 0;
#pragma unroll
            for (int i = 0; i < 32; i++) clg += (u[i] > Uk) ? 1 : 0;
            int cGT = __reduce_add_sync(0xffffffffu, clg);
            int rem = k - cGT;                  // >= 1
            int ilo = 0, ihi = ROWLEN, mI = ROWLEN;
            for (;;) {
                mI = (ilo + ihi + 1) >> 1;
                int ct = 0;
#pragma unroll
                for (int mm = 0; mm < 8; mm++) {
                    uint4 t = *(const uint4*)(smem + 4096 + (mm * 512 + lane * 16));
                    ct += (u[mm*4+0] == Uk && (int)(t.x >> 8) < mI) ? 1 : 0;
                    ct += (u[mm*4+1] == Uk && (int)(t.y >> 8) < mI) ? 1 : 0;
                    ct += (u[mm*4+2] == Uk && (int)(t.z >> 8) < mI) ? 1 : 0;
                    ct += (u[mm*4+3] == Uk && (int)(t.w >> 8) < mI) ? 1 : 0;
                }
                int c = __reduce_add_sync(0xffffffffu, ct);
                if (c == rem) break;            // unique indices -> always reachable
                if (c < rem) ilo = mI; else ihi = mI - 1;
            }
#pragma unroll
            for (int mm = 0; mm < 8; mm++) {
                uint4 t = *(const uint4*)(smem + 4096 + (mm * 512 + lane * 16));
                if (u[mm*4+0] > Uk || (u[mm*4+0] == Uk && (int)(t.x >> 8) < mI)) win |= 1u << (mm*4+0);
                if (u[mm*4+1] > Uk || (u[mm*4+1] == Uk && (int)(t.y >> 8) < mI)) win |= 1u << (mm*4+1);
                if (u[mm*4+2] > Uk || (u[mm*4+2] == Uk && (int)(t.z >> 8) < mI)) win |= 1u << (mm*4+2);
                if (u[mm*4+3] > Uk || (u[mm*4+3] == Uk && (int)(t.w >> 8) < mI)) win |= 1u << (mm*4+3);
            }
        }
    } else if (wid != 0) {
        // ---- clip + dequantize epilogue (warps 1-7, concurrent with warp 0) ----
        float4* __restrict__ orow4 = (float4*)orow;
        const int* s_ri = (const int*)s_r;
        for (int i = tid - 32; i < NV4; i += NT - 32) {
            int p = s_ri[i];
            p = __vmins4(__vmaxs4(p, 0xF8F8F8F8), 0x07070707);   // clip bytes to [-8,7]
            float4 o;
            o.x = fmaf((float)(int)(signed char)(p),       inv, zpinv);
            o.y = fmaf((float)(int)(signed char)(p >> 8),  inv, zpinv);
            o.z = fmaf((float)(int)(signed char)(p >> 16), inv, zpinv);
            o.w = fmaf((float)(int)(signed char)(p >> 24), inv, zpinv);
            orow4[i] = o;
        }
    }
    __syncthreads();   // barrier #3: epilogue STGs ordered before the patch

    // ---- warp 0 patches the flipped elements directly in GMEM ----
    if (wid == 0 && k > 0 && win) {
#pragma unroll
        for (int mm = 0; mm < 8; mm++) {
            uint4 t = *(const uint4*)(smem + 4096 + (mm * 512 + lane * 16));
#pragma unroll
            for (int q = 0; q < 4; q++) {
                if ((win >> (mm * 4 + q)) & 1u) {
                    unsigned ivv = (q == 0) ? t.x : (q == 1) ? t.y : (q == 2) ? t.z : t.w;
                    int   idx = (int)(ivv >> 8);
                    float vf  = (float)((int)(ivv & 0xFFu) - 32);
                    orow[idx] = fmaf(fminf(7.f, fmaxf(-8.f, vf)), inv, zpinv);
                }
            }
        }
    }
}

extern "C" void kernel_launch(void* const* d_in, const int* in_sizes, int n_in,
                              void* d_out, int out_size)
{
    const float* w = (const float*)d_in[0];
    float* out = (float*)d_out;
    squant_kernel<<<NROWS, NT, SMEM_BYTES>>>(w, out);
}